// round 14
// baseline (speedup 1.0000x reference)
#include <cuda_runtime.h>
#include <cuda_bf16.h>

// Per-channel class frequencies (compile-time constants from the reference).
__constant__ float c_W[23] = {
    0.0012597430655963838f, 0.0004919313290455535f, 0.0021106513104319356f,
    0.0007678117365508301f, 0.004719881670572202f,  0.000372272357115554f,
    0.029090425620315438f,  0.010056339432617042f,  0.0034817436971298467f,
    0.0003057951504877765f, 0.003995280118329428f,  8.808229878180519e-05f,
    0.012070598793438699f,  0.016788818533845208f,  0.0017832510677901316f,
    0.0008758371973209686f, 0.0005933090691529143f, 0.0031992155689617922f,
    0.003212511010287348f,  0.0016685778863572154f, 0.0009356666832859684f,
    0.0010985358395240233f, 0.00103372056306194f
};

// 592 blocks x 512 threads = 4 CTAs/SM x 148 SMs, 64 warps/SM, single
// balanced wave. Same warp count as 1184x256 but half the CTA overhead
// (R10 measured this main loop marginally fastest).
#define NBLOCKS 592
#define NTHREADS 512
#define LN2F 0.6931471805599453f

// Scratch (no allocations allowed). g_acc is reset to 0 by the last-ticket
// block every run, and g_count self-wraps via atomicInc -> graph-replay safe.
__device__ double   g_acc   = 0.0;
__device__ unsigned g_count = 0;

__global__ __launch_bounds__(NTHREADS, 4)
void bce_fused_kernel(const float4* __restrict__ x4,
                      const int4*   __restrict__ l4,
                      int n_vec, int rem,
                      const float* __restrict__ x_tail,
                      const int*   __restrict__ l_tail,
                      int tail_base,
                      float* __restrict__ out, float inv_n) {
    __shared__ float s_w0[23];   // ln2*(W+1)   : weight when label==0
    __shared__ float s_w1[23];   // ln2*(1+1/W) : weight when label==1
    __shared__ float s_part[NTHREADS / 32];

    const int t = threadIdx.x;
    if (t < 23) {
        float w = c_W[t];
        s_w0[t] = LN2F * (w + 1.0f);
        s_w1[t] = LN2F * (1.0f + __frcp_rn(w));
    }
    __syncthreads();

    const int stride = NBLOCKS * NTHREADS;   // 303104 (same as 1184x256)
    const int gtid   = blockIdx.x * NTHREADS + t;

    // Channel of the first element of this thread's first vector, and the
    // per-iteration advance (4*stride mod 23).
    int c_base = (int)((4ll * (long long)gtid) % 23);
    const int d = (int)((4ll * (long long)stride) % 23);

    float acc = 0.0f;

    // Plain grid-stride loop, compiler-chosen unroll (empirical optimum).
    for (int v = gtid; v < n_vec; v += stride) {
        float4 xv = __ldg(&x4[v]);
        int4   lv = __ldg(&l4[v]);

        int c = c_base;
        c_base += d; if (c_base >= 23) c_base -= 23;

        float xs[4] = { xv.x, xv.y, xv.z, xv.w };
        int   ls[4] = { lv.x, lv.y, lv.z, lv.w };
        #pragma unroll
        for (int j = 0; j < 4; ++j) {
            bool  pos = (ls[j] > 0);
            float arg = pos ? xs[j] : (1.0f - xs[j]);
            const float* tab = pos ? s_w1 : s_w0;   // one LDS per element
            acc = fmaf(tab[c], -__log2f(arg), acc);
            c = (c == 22) ? 0 : (c + 1);
        }
    }

    // Scalar tail (n % 4 elements; 0 for B*C = 23e6 but kept for generality).
    if (gtid < rem) {
        int   i   = tail_base + gtid;
        int   lab = __ldg(&l_tail[gtid]);
        float xv  = __ldg(&x_tail[gtid]);
        int   c   = i % 23;
        bool  pos = (lab > 0);
        float arg = pos ? xv : (1.0f - xv);
        const float* tab = pos ? s_w1 : s_w0;
        acc = fmaf(tab[c], -__log2f(arg), acc);
    }

    // Intra-block reduce (f32).
    #pragma unroll
    for (int o = 16; o > 0; o >>= 1)
        acc += __shfl_down_sync(0xffffffffu, acc, o);

    const int lane = t & 31, wid = t >> 5;
    if (lane == 0) s_part[wid] = acc;
    __syncthreads();

    if (t == 0) {
        float b = 0.0f;
        #pragma unroll
        for (int w = 0; w < NTHREADS / 32; ++w) b += s_part[w];
        // Accumulate in double directly (overlaps with other blocks' compute).
        atomicAdd(&g_acc, (double)b);
        __threadfence();
        unsigned ticket = atomicInc(&g_count, NBLOCKS - 1); // wraps to 0
        if (ticket == NBLOCKS - 1) {
            // All blocks' atomicAdds precede their atomicInc; we're last.
            double tot = g_acc;
            out[0] = (float)(tot * (double)inv_n);
            g_acc = 0.0;            // reset for next graph replay
            __threadfence();
        }
    }
}

extern "C" void kernel_launch(void* const* d_in, const int* in_sizes, int n_in,
                              void* d_out, int out_size) {
    const float* x = (const float*)d_in[0];
    const int*   l = (const int*)d_in[1];
    float* out = (float*)d_out;

    long long n = (long long)in_sizes[0];   // total elements (B*C) = 23e6
    int n_vec = (int)(n >> 2);
    int rem = (int)(n & 3);
    int tail_base = n_vec << 2;

    bce_fused_kernel<<<NBLOCKS, NTHREADS>>>(
        (const float4*)x, (const int4*)l, n_vec, rem,
        x + (long long)tail_base, l + (long long)tail_base, tail_base,
        out, 1.0f / (float)n);
}

// round 15
// speedup vs baseline: 1.0500x; 1.0500x over previous
#include <cuda_runtime.h>
#include <cuda_bf16.h>

// Per-channel class frequencies (compile-time constants from the reference).
__constant__ float c_W[23] = {
    0.0012597430655963838f, 0.0004919313290455535f, 0.0021106513104319356f,
    0.0007678117365508301f, 0.004719881670572202f,  0.000372272357115554f,
    0.029090425620315438f,  0.010056339432617042f,  0.0034817436971298467f,
    0.0003057951504877765f, 0.003995280118329428f,  8.808229878180519e-05f,
    0.012070598793438699f,  0.016788818533845208f,  0.0017832510677901316f,
    0.0008758371973209686f, 0.0005933090691529143f, 0.0031992155689617922f,
    0.003212511010287348f,  0.0016685778863572154f, 0.0009356666832859684f,
    0.0010985358395240233f, 0.00103372056306194f
};

// NT = 736 = 23*32: 4*NT ≡ 0 (mod 23), so per-thread channels are
// loop-invariant for ANY block count -> register-resident weights.
// NB = 296 = 2 CTAs x 148 SMs: single perfectly balanced wave
// (46 warps/SM; R12 proved 32 warps/SM already sustains peak BW).
#define NBLOCKS 296
#define NTHREADS 736
#define NWARPS (NTHREADS / 32)
#define LN2F 0.6931471805599453f

// Scratch (no allocations allowed). g_acc is reset to 0 by the last-ticket
// block every run, and g_count self-wraps via atomicInc -> graph-replay safe.
__device__ double   g_acc   = 0.0;
__device__ unsigned g_count = 0;

__global__ __launch_bounds__(NTHREADS, 2)
void bce_fused_kernel(const float4* __restrict__ x4,
                      const int4*   __restrict__ l4,
                      int n_vec, int rem,
                      const float* __restrict__ x_tail,
                      const int*   __restrict__ l_tail,
                      int tail_base,
                      float* __restrict__ out, float inv_n) {
    __shared__ float s_w0[23];   // ln2*(W+1)   : weight when label==0
    __shared__ float s_w1[23];   // ln2*(1+1/W) : weight when label==1
    __shared__ float s_part[NWARPS];

    const int t = threadIdx.x;
    if (t < 23) {
        float w = c_W[t];
        s_w0[t] = LN2F * (w + 1.0f);
        s_w1[t] = LN2F * (1.0f + __frcp_rn(w));
    }
    __syncthreads();

    const int stride = NBLOCKS * NTHREADS;   // 217856; 4*stride % 23 == 0
    const int gtid   = blockIdx.x * NTHREADS + t;

    // Fixed channels for this thread (loop-invariant by construction).
    int c0 = (int)((4ll * (long long)gtid) % 23);
    int c1 = c0 + 1; if (c1 >= 23) c1 -= 23;
    int c2 = c1 + 1; if (c2 >= 23) c2 -= 23;
    int c3 = c2 + 1; if (c3 >= 23) c3 -= 23;

    // 8 weights in registers — no LDS, no channel math in the hot loop.
    const float w00 = s_w0[c0], w10 = s_w1[c0];
    const float w01 = s_w0[c1], w11 = s_w1[c1];
    const float w02 = s_w0[c2], w12 = s_w1[c2];
    const float w03 = s_w0[c3], w13 = s_w1[c3];

    float acc = 0.0f;

    // Plain grid-stride loop, compiler-chosen unroll, default __ldg caching
    // (the empirically optimal load schedule from R8/R13).
    for (int v = gtid; v < n_vec; v += stride) {
        float4 xv = __ldg(&x4[v]);
        int4   lv = __ldg(&l4[v]);

        bool p0 = lv.x > 0, p1 = lv.y > 0, p2 = lv.z > 0, p3 = lv.w > 0;
        acc = fmaf(p0 ? w10 : w00, -__log2f(p0 ? xv.x : 1.0f - xv.x), acc);
        acc = fmaf(p1 ? w11 : w01, -__log2f(p1 ? xv.y : 1.0f - xv.y), acc);
        acc = fmaf(p2 ? w12 : w02, -__log2f(p2 ? xv.z : 1.0f - xv.z), acc);
        acc = fmaf(p3 ? w13 : w03, -__log2f(p3 ? xv.w : 1.0f - xv.w), acc);
    }

    // Scalar tail (n % 4 elements; 0 for B*C = 23e6 but kept for generality).
    if (gtid < rem) {
        int   i   = tail_base + gtid;
        int   lab = __ldg(&l_tail[gtid]);
        float xv  = __ldg(&x_tail[gtid]);
        int   c   = i % 23;
        bool  pos = (lab > 0);
        float arg = pos ? xv : (1.0f - xv);
        acc = fmaf(pos ? s_w1[c] : s_w0[c], -__log2f(arg), acc);
    }

    // Intra-block reduce (f32).
    #pragma unroll
    for (int o = 16; o > 0; o >>= 1)
        acc += __shfl_down_sync(0xffffffffu, acc, o);

    const int lane = t & 31, wid = t >> 5;
    if (lane == 0) s_part[wid] = acc;
    __syncthreads();

    if (t == 0) {
        float b = 0.0f;
        #pragma unroll
        for (int w = 0; w < NWARPS; ++w) b += s_part[w];
        // Accumulate in double directly (overlaps with other blocks' compute).
        atomicAdd(&g_acc, (double)b);
        __threadfence();
        unsigned ticket = atomicInc(&g_count, NBLOCKS - 1); // wraps to 0
        if (ticket == NBLOCKS - 1) {
            // All blocks' atomicAdds precede their atomicInc; we're last.
            double tot = g_acc;
            out[0] = (float)(tot * (double)inv_n);
            g_acc = 0.0;            // reset for next graph replay
            __threadfence();
        }
    }
}

extern "C" void kernel_launch(void* const* d_in, const int* in_sizes, int n_in,
                              void* d_out, int out_size) {
    const float* x = (const float*)d_in[0];
    const int*   l = (const int*)d_in[1];
    float* out = (float*)d_out;

    long long n = (long long)in_sizes[0];   // total elements (B*C) = 23e6
    int n_vec = (int)(n >> 2);
    int rem = (int)(n & 3);
    int tail_base = n_vec << 2;

    bce_fused_kernel<<<NBLOCKS, NTHREADS>>>(
        (const float4*)x, (const int4*)l, n_vec, rem,
        x + (long long)tail_base, l + (long long)tail_base, tail_base,
        out, 1.0f / (float)n);
}